// round 3
// baseline (speedup 1.0000x reference)
#include <cuda_runtime.h>
#include <math.h>

// Problem constants (fixed shapes from the reference)
#define B   64
#define C   256
#define HW  3136          // 56*56
#define HW4 784           // HW / 4 (float4 count per channel)
#define NCH (B * C)       // 16384 channels
#define RDIM 16           // C / r
#define KPOS 204          // round(0.8*256)=205 -> 0-indexed 204

// Scratch (allocation-free rule: __device__ globals)
__device__ float g_mean[NCH];
__device__ float g_mask[NCH];

// ---------------------------------------------------------------------------
// Kernel 1: per-channel mean. One warp per channel, float4 streaming loads.
// Two accumulators to expose more memory-level parallelism per lane.
// ---------------------------------------------------------------------------
__global__ void se_mean_kernel(const float* __restrict__ x) {
    int gwarp = (blockIdx.x * blockDim.x + threadIdx.x) >> 5;
    int lane  = threadIdx.x & 31;
    if (gwarp >= NCH) return;

    const float4* p = reinterpret_cast<const float4*>(x + (size_t)gwarp * HW);
    float s0 = 0.0f, s1 = 0.0f;
    // HW4 = 784 = 32*24 + 16 -> lanes do 24 or 25 iters; unroll pairs of strides
    int i = lane;
    #pragma unroll 4
    for (; i + 32 < HW4; i += 64) {
        float4 a = p[i];
        float4 b = p[i + 32];
        s0 += (a.x + a.y) + (a.z + a.w);
        s1 += (b.x + b.y) + (b.z + b.w);
    }
    if (i < HW4) {
        float4 a = p[i];
        s0 += (a.x + a.y) + (a.z + a.w);
    }
    float s = s0 + s1;
    #pragma unroll
    for (int o = 16; o > 0; o >>= 1)
        s += __shfl_xor_sync(0xffffffffu, s, o);
    if (lane == 0)
        g_mean[gwarp] = s * (1.0f / (float)HW);
}

// ---------------------------------------------------------------------------
// Kernel 2: SE MLP + per-row rank selection -> mask. One block per batch row.
// ---------------------------------------------------------------------------
__global__ void se_mlp_mask_kernel(const float* __restrict__ W1,
                                   const float* __restrict__ W2) {
    __shared__ float s_mean[C];
    __shared__ float s_hidden[RDIM];
    __shared__ float s_y[C];
    __shared__ float s_thresh;

    int b = blockIdx.x;
    int t = threadIdx.x;     // 0..255

    s_mean[t] = g_mean[b * C + t];
    __syncthreads();

    // hidden[j] = relu( sum_c mean[c] * W1[j, c] ), 16 threads do full dots
    if (t < RDIM) {
        float acc = 0.0f;
        const float* w = W1 + t * C;
        #pragma unroll 8
        for (int c = 0; c < C; ++c)
            acc = fmaf(s_mean[c], w[c], acc);
        s_hidden[t] = fmaxf(acc, 0.0f);
    }
    __syncthreads();

    // y[t] = sigmoid( sum_j hidden[j] * W2[t, j] )
    {
        float acc = 0.0f;
        const float* w = W2 + t * RDIM;
        #pragma unroll
        for (int j = 0; j < RDIM; ++j)
            acc = fmaf(s_hidden[j], w[j], acc);
        s_y[t] = 1.0f / (1.0f + __expf(-acc));
    }
    __syncthreads();

    // rank of y[t] with (value, index) tiebreak; exactly one thread has rank KPOS
    float yt = s_y[t];
    int rank = 0;
    #pragma unroll 8
    for (int j = 0; j < C; ++j) {
        float yj = s_y[j];
        rank += (yj < yt) || (yj == yt && j < t);
    }
    if (rank == KPOS) s_thresh = yt;
    __syncthreads();

    g_mask[b * C + t] = (yt <= s_thresh) ? 1.0f : 0.0f;
}

// ---------------------------------------------------------------------------
// Kernel 3: out = x * mask (per-channel scalar). One block per channel.
// mask==0 channels: write zeros without reading x (saves ~20% of 2nd read).
// ---------------------------------------------------------------------------
__global__ void se_scale_kernel(const float* __restrict__ x,
                                float* __restrict__ out) {
    int ch = blockIdx.x;
    float m = g_mask[ch];

    const float4* in = reinterpret_cast<const float4*>(x + (size_t)ch * HW);
    float4* o = reinterpret_cast<float4*>(out + (size_t)ch * HW);

    if (m == 0.0f) {
        float4 z = make_float4(0.f, 0.f, 0.f, 0.f);
        for (int i = threadIdx.x; i < HW4; i += blockDim.x)
            o[i] = z;
    } else {
        // m == 1.0f -> pure copy
        for (int i = threadIdx.x; i < HW4; i += blockDim.x)
            o[i] = in[i];
    }
}

// ---------------------------------------------------------------------------
extern "C" void kernel_launch(void* const* d_in, const int* in_sizes, int n_in,
                              void* d_out, int out_size) {
    const float* x  = (const float*)d_in[0];   // [64,256,56,56]
    const float* W1 = (const float*)d_in[1];   // [16,256]
    const float* W2 = (const float*)d_in[2];   // [256,16]
    float* out = (float*)d_out;

    // 8 warps per block -> 2048 blocks cover 16384 channels
    se_mean_kernel<<<NCH / 8, 256>>>(x);
    se_mlp_mask_kernel<<<B, C>>>(W1, W2);
    se_scale_kernel<<<NCH, 128>>>(x, out);
}

// round 4
// speedup vs baseline: 1.0025x; 1.0025x over previous
#include <cuda_runtime.h>
#include <math.h>

// Problem constants (fixed shapes from the reference)
#define B   64
#define C   256
#define HW  3136          // 56*56
#define HW4 784           // HW / 4 (float4 count per channel)
#define NCH (B * C)       // 16384 channels
#define RDIM 16           // C / r
#define KPOS 204          // round(0.8*256)=205 -> 0-indexed 204

// Scratch (allocation-free rule: __device__ globals)
__device__ float g_mean[NCH];
__device__ float g_mask[NCH];

// ---------------------------------------------------------------------------
// Kernel 1: per-channel mean. One warp per channel, float4 streaming loads.
// Two accumulators to expose more memory-level parallelism per lane.
// ---------------------------------------------------------------------------
__global__ void se_mean_kernel(const float* __restrict__ x) {
    int gwarp = (blockIdx.x * blockDim.x + threadIdx.x) >> 5;
    int lane  = threadIdx.x & 31;
    if (gwarp >= NCH) return;

    const float4* p = reinterpret_cast<const float4*>(x + (size_t)gwarp * HW);
    float s0 = 0.0f, s1 = 0.0f;
    // HW4 = 784 = 32*24 + 16 -> lanes do 24 or 25 iters; unroll pairs of strides
    int i = lane;
    #pragma unroll 4
    for (; i + 32 < HW4; i += 64) {
        float4 a = p[i];
        float4 b = p[i + 32];
        s0 += (a.x + a.y) + (a.z + a.w);
        s1 += (b.x + b.y) + (b.z + b.w);
    }
    if (i < HW4) {
        float4 a = p[i];
        s0 += (a.x + a.y) + (a.z + a.w);
    }
    float s = s0 + s1;
    #pragma unroll
    for (int o = 16; o > 0; o >>= 1)
        s += __shfl_xor_sync(0xffffffffu, s, o);
    if (lane == 0)
        g_mean[gwarp] = s * (1.0f / (float)HW);
}

// ---------------------------------------------------------------------------
// Kernel 2: SE MLP + per-row rank selection -> mask. One block per batch row.
// ---------------------------------------------------------------------------
__global__ void se_mlp_mask_kernel(const float* __restrict__ W1,
                                   const float* __restrict__ W2) {
    __shared__ float s_mean[C];
    __shared__ float s_hidden[RDIM];
    __shared__ float s_y[C];
    __shared__ float s_thresh;

    int b = blockIdx.x;
    int t = threadIdx.x;     // 0..255

    s_mean[t] = g_mean[b * C + t];
    __syncthreads();

    // hidden[j] = relu( sum_c mean[c] * W1[j, c] ), 16 threads do full dots
    if (t < RDIM) {
        float acc = 0.0f;
        const float* w = W1 + t * C;
        #pragma unroll 8
        for (int c = 0; c < C; ++c)
            acc = fmaf(s_mean[c], w[c], acc);
        s_hidden[t] = fmaxf(acc, 0.0f);
    }
    __syncthreads();

    // y[t] = sigmoid( sum_j hidden[j] * W2[t, j] )
    {
        float acc = 0.0f;
        const float* w = W2 + t * RDIM;
        #pragma unroll
        for (int j = 0; j < RDIM; ++j)
            acc = fmaf(s_hidden[j], w[j], acc);
        s_y[t] = 1.0f / (1.0f + __expf(-acc));
    }
    __syncthreads();

    // rank of y[t] with (value, index) tiebreak; exactly one thread has rank KPOS
    float yt = s_y[t];
    int rank = 0;
    #pragma unroll 8
    for (int j = 0; j < C; ++j) {
        float yj = s_y[j];
        rank += (yj < yt) || (yj == yt && j < t);
    }
    if (rank == KPOS) s_thresh = yt;
    __syncthreads();

    g_mask[b * C + t] = (yt <= s_thresh) ? 1.0f : 0.0f;
}

// ---------------------------------------------------------------------------
// Kernel 3: out = x * mask (per-channel scalar). One block per channel.
// mask==0 channels: write zeros without reading x (saves ~20% of 2nd read).
// ---------------------------------------------------------------------------
__global__ void se_scale_kernel(const float* __restrict__ x,
                                float* __restrict__ out) {
    int ch = blockIdx.x;
    float m = g_mask[ch];

    const float4* in = reinterpret_cast<const float4*>(x + (size_t)ch * HW);
    float4* o = reinterpret_cast<float4*>(out + (size_t)ch * HW);

    if (m == 0.0f) {
        float4 z = make_float4(0.f, 0.f, 0.f, 0.f);
        for (int i = threadIdx.x; i < HW4; i += blockDim.x)
            o[i] = z;
    } else {
        // m == 1.0f -> pure copy
        for (int i = threadIdx.x; i < HW4; i += blockDim.x)
            o[i] = in[i];
    }
}

// ---------------------------------------------------------------------------
extern "C" void kernel_launch(void* const* d_in, const int* in_sizes, int n_in,
                              void* d_out, int out_size) {
    const float* x  = (const float*)d_in[0];   // [64,256,56,56]
    const float* W1 = (const float*)d_in[1];   // [16,256]
    const float* W2 = (const float*)d_in[2];   // [256,16]
    float* out = (float*)d_out;

    // 8 warps per block -> 2048 blocks cover 16384 channels
    se_mean_kernel<<<NCH / 8, 256>>>(x);
    se_mlp_mask_kernel<<<B, C>>>(W1, W2);
    se_scale_kernel<<<NCH, 128>>>(x, out);
}